// round 1
// baseline (speedup 1.0000x reference)
#include <cuda_runtime.h>
#include <cuda_bf16.h>

#define N_NODES 100000
#define N_EDGES 1600000
#define D 128            // D_IN == D_OUT == 128

// ---------------- static device scratch (no allocations allowed) ----------------
__device__ float g_h[N_NODES * D];       // x @ W
__device__ float g_dis[N_NODES];         // deg^{-1/2}
__device__ int   g_deg[N_NODES];         // in-degree (edges only, self-loop added in formula)
__device__ int   g_rowptr[N_NODES + 1];  // CSR row pointers (keyed by dst)
__device__ int   g_cursor[N_NODES];      // scatter cursors
__device__ int   g_col[N_EDGES];         // CSR column (src) indices
#define SCAN_B 1024
#define N_SCAN_BLOCKS ((N_NODES + SCAN_B - 1) / SCAN_B)   // 98
__device__ int   g_bsums[N_SCAN_BLOCKS];

// ---------------- kernels ----------------

__global__ void k_init_deg() {
    int i = blockIdx.x * blockDim.x + threadIdx.x;
    if (i < N_NODES) g_deg[i] = 0;
}

__global__ void k_count(const int* __restrict__ dst) {
    int e = blockIdx.x * blockDim.x + threadIdx.x;
    if (e < N_EDGES) atomicAdd(&g_deg[dst[e]], 1);
}

__global__ void k_dis() {
    int i = blockIdx.x * blockDim.x + threadIdx.x;
    if (i < N_NODES) g_dis[i] = rsqrtf((float)(g_deg[i] + 1));  // +1 self loop
}

// per-block inclusive scan -> store exclusive prefix (pre-offset) + block total
__global__ void k_scan1() {
    __shared__ int s[SCAN_B];
    int tid = threadIdx.x;
    int gid = blockIdx.x * SCAN_B + tid;
    int v = (gid < N_NODES) ? g_deg[gid] : 0;
    s[tid] = v;
    __syncthreads();
    #pragma unroll
    for (int off = 1; off < SCAN_B; off <<= 1) {
        int t = (tid >= off) ? s[tid - off] : 0;
        __syncthreads();
        s[tid] += t;
        __syncthreads();
    }
    if (gid < N_NODES) g_rowptr[gid] = s[tid] - v;   // exclusive, local
    if (tid == SCAN_B - 1) g_bsums[blockIdx.x] = s[tid];
}

__global__ void k_scan2() {
    int run = 0;
    for (int b = 0; b < N_SCAN_BLOCKS; b++) {
        int t = g_bsums[b];
        g_bsums[b] = run;
        run += t;
    }
    g_rowptr[N_NODES] = N_EDGES;
}

__global__ void k_scan3() {
    int gid = blockIdx.x * SCAN_B + threadIdx.x;
    if (gid < N_NODES) {
        int r = g_rowptr[gid] + g_bsums[blockIdx.x];
        g_rowptr[gid] = r;
        g_cursor[gid] = r;
    }
}

__global__ void k_scatter(const int* __restrict__ src, const int* __restrict__ dst) {
    int e = blockIdx.x * blockDim.x + threadIdx.x;
    if (e < N_EDGES) {
        int d = dst[e];
        int pos = atomicAdd(&g_cursor[d], 1);
        g_col[pos] = src[e];
    }
}

// h = x @ W   (fp32).  Block: 256 threads, 32 rows. Thread (jq = t&31, rg = t>>5)
// computes rows rg*4..rg*4+3, columns jq*4..jq*4+3 (4x4 register tile).
__global__ void __launch_bounds__(256) k_gemm(const float* __restrict__ x,
                                              const float* __restrict__ W) {
    __shared__ float xs[32][D];
    int row0 = blockIdx.x * 32;
    // cooperative load of 32 x-rows (coalesced float4)
    {
        const float4* x4 = (const float4*)(x + (size_t)row0 * D);
        float4* xs4 = (float4*)&xs[0][0];
        #pragma unroll
        for (int idx = threadIdx.x; idx < 32 * (D / 4); idx += 256)
            xs4[idx] = x4[idx];
    }
    __syncthreads();

    int jq = threadIdx.x & 31;
    int rg = threadIdx.x >> 5;
    float4 acc[4];
    #pragma unroll
    for (int r = 0; r < 4; r++) acc[r] = make_float4(0.f, 0.f, 0.f, 0.f);

    const float4* W4 = (const float4*)W;  // W[k][j], row k = 32 float4
    #pragma unroll 4
    for (int k = 0; k < D; k++) {
        float4 w = __ldg(&W4[k * 32 + jq]);
        #pragma unroll
        for (int r = 0; r < 4; r++) {
            float xv = xs[(rg << 2) + r][k];
            acc[r].x = fmaf(xv, w.x, acc[r].x);
            acc[r].y = fmaf(xv, w.y, acc[r].y);
            acc[r].z = fmaf(xv, w.z, acc[r].z);
            acc[r].w = fmaf(xv, w.w, acc[r].w);
        }
    }
    float4* h4 = (float4*)g_h;
    #pragma unroll
    for (int r = 0; r < 4; r++) {
        int row = row0 + (rg << 2) + r;
        h4[(size_t)row * 32 + jq] = acc[r];
    }
}

// One warp per node. acc = dis[i]*h[i] + sum_{s in N(i)} dis[s]*h[s];
// out = relu(dis[i]*acc + b).  col/dis prefetched across lanes, shfl-broadcast.
__global__ void __launch_bounds__(256) k_agg(const float* __restrict__ b,
                                             float* __restrict__ out) {
    int node = blockIdx.x * 8 + (threadIdx.x >> 5);
    int lane = threadIdx.x & 31;
    if (node >= N_NODES) return;

    const float4* h4 = (const float4*)g_h;
    float di = g_dis[node];
    float4 hv = h4[(size_t)node * 32 + lane];
    float4 acc;
    acc.x = di * hv.x; acc.y = di * hv.y; acc.z = di * hv.z; acc.w = di * hv.w;

    int beg = g_rowptr[node];
    int end = g_rowptr[node + 1];
    int cnt = end - beg;

    for (int base = 0; base < cnt; base += 32) {
        int myi = base + lane;
        int sc = 0; float ns = 0.f;
        if (myi < cnt) {
            sc = __ldg(&g_col[beg + myi]);
            ns = __ldg(&g_dis[sc]);
        }
        int m = min(32, cnt - base);
        for (int t = 0; t < m; t++) {
            int   s  = __shfl_sync(0xffffffffu, sc, t);
            float nn = __shfl_sync(0xffffffffu, ns, t);
            float4 v = __ldg(&h4[(size_t)s * 32 + lane]);
            acc.x = fmaf(nn, v.x, acc.x);
            acc.y = fmaf(nn, v.y, acc.y);
            acc.z = fmaf(nn, v.z, acc.z);
            acc.w = fmaf(nn, v.w, acc.w);
        }
    }

    float4 bv = __ldg(&((const float4*)b)[lane]);
    float4 o;
    o.x = fmaxf(fmaf(di, acc.x, bv.x), 0.f);
    o.y = fmaxf(fmaf(di, acc.y, bv.y), 0.f);
    o.z = fmaxf(fmaf(di, acc.z, bv.z), 0.f);
    o.w = fmaxf(fmaf(di, acc.w, bv.w), 0.f);
    ((float4*)out)[(size_t)node * 32 + lane] = o;
}

// ---------------- launch ----------------
extern "C" void kernel_launch(void* const* d_in, const int* in_sizes, int n_in,
                              void* d_out, int out_size) {
    const float* x   = (const float*)d_in[0];
    const int*   ei  = (const int*)d_in[1];     // [2, E] row-major
    const float* W   = (const float*)d_in[2];
    const float* b   = (const float*)d_in[3];
    float* out = (float*)d_out;

    const int* src = ei;
    const int* dst = ei + N_EDGES;

    const int TPB = 256;
    int gN = (N_NODES + TPB - 1) / TPB;   // 391
    int gE = (N_EDGES + TPB - 1) / TPB;   // 6250

    k_init_deg<<<gN, TPB>>>();
    k_count<<<gE, TPB>>>(dst);
    k_dis<<<gN, TPB>>>();
    k_scan1<<<N_SCAN_BLOCKS, SCAN_B>>>();
    k_scan2<<<1, 1>>>();
    k_scan3<<<N_SCAN_BLOCKS, SCAN_B>>>();
    k_scatter<<<gE, TPB>>>(src, dst);
    k_gemm<<<N_NODES / 32, 256>>>(x, W);          // 3125 blocks (100000 = 32*3125)
    k_agg<<<(N_NODES + 7) / 8, 256>>>(b, out);    // 12500 blocks
}